// round 16
// baseline (speedup 1.0000x reference)
#include <cuda_runtime.h>
#include <cuda_fp16.h>
#include <cstdint>

#define BATCH 16
#define NW3   589824
#define NW1   65280

// ---------------- scratch ----------------
__device__ __half g_xh[41828352];           // padded NHWC input, fp16
__device__ __half g_hh[34918400];           // hidden NHWC, fp16
__device__ __half g_w3h[5 * 9 * 256 * 256]; // [lvl][tap][ic][oc] ternary fp16
__device__ __half g_w1h[5 * 256 * 256];     // [lvl][ic][oc(255->0 pad)]
__device__ float    g_scale3[5 * 256];
__device__ float    g_bias3 [5 * 256];
__device__ float    g_scale[10];
__device__ unsigned g_hist[10][2][2048];
__device__ unsigned g_prefix[10][2];
__device__ unsigned g_remain[10][2];
__device__ unsigned g_done[3][10];

// ---------------- compile-time per-level tables ----------------
__constant__ int c_H[5]    = {80, 40, 20, 10, 5};
__constant__ int c_PH[5]   = {82, 42, 26, 18, 10};
__constant__ int c_PW[5]   = {82, 50, 34, 18, 18};
__constant__ int c_TX[5]   = {5, 3, 2, 1, 1};
__constant__ int c_xOff[5] = {0, 27541504, 36143104, 39763968, 41091072};
__constant__ int c_hOff[5] = {0, 26214400, 32768000, 34406400, 34816000};
__constant__ int c_a85[5]  = {0, 1632000, 2040000, 2142000, 2167500};
__constant__ int c_HW[5]   = {6400, 1600, 400, 100, 25};
__constant__ int c_XC[5]   = {3, 2, 2, 1, 1};

__device__ __forceinline__ uint32_t smem_u32(const void* p) {
    uint32_t a;
    asm("{ .reg .u64 t; cvta.to.shared.u64 t, %1; cvt.u32.u64 %0, t; }" : "=r"(a) : "l"(p));
    return a;
}
#define CP_COMMIT() asm volatile("cp.async.commit_group;" ::: "memory")
#define CP_WAIT2()  asm volatile("cp.async.wait_group 2;" ::: "memory")
#define CP_WAIT1()  asm volatile("cp.async.wait_group 1;" ::: "memory")
#define CP_WAIT0()  asm volatile("cp.async.wait_group 0;" ::: "memory")
__device__ __forceinline__ void cpa16(uint32_t dst, const void* src) {
    asm volatile("cp.async.ca.shared.global [%0], [%1], 16;" :: "r"(dst), "l"(src) : "memory");
}
__device__ __forceinline__ void cpa16z(uint32_t dst, const void* src, int sz) {
    asm volatile("cp.async.ca.shared.global [%0], [%1], 16, %2;" :: "r"(dst), "l"(src), "r"(sz) : "memory");
}
#define MMA16816(c, a0, a1, a2, a3, b0, b1)                              \
    asm volatile("mma.sync.aligned.m16n8k16.row.col.f32.f16.f16.f32 "    \
        "{%0,%1,%2,%3}, {%4,%5,%6,%7}, {%8,%9}, {%0,%1,%2,%3};"          \
        : "+f"((c)[0]), "+f"((c)[1]), "+f"((c)[2]), "+f"((c)[3])         \
        : "r"(a0), "r"(a1), "r"(a2), "r"(a3), "r"(b0), "r"(b1))

// conv3 smem (2 blocks/SM): sc(1024)|bs(1024) | A buf0/1 (14400 each: 180 rows x 80B) | B buf0..2 (26112 each = 3 taps)
#define C3_A(b)     (2048 + (b) * 14400)
#define C3_B(b)     (30848 + (b) * 26112)
#define SMEM_C3     109184
// conv1 smem: bi(2048) | A buf0..3 (10240 each) | B buf0..3 (16896 each: 32k x 256oc, row 528B)
#define S1_A(b)     (2048 + (b) * 10240)
#define S1_B(b)     (43008 + (b) * 16896)
#define SMEM_C1     110592

// ---------------- median radix-select: hist + last-block scan fused ----------------
__global__ void ph_histscan(const float* __restrict__ w3, const float* __restrict__ w1,
                            int shift, int bits, int pass) {
    extern __shared__ unsigned sh[];
    __shared__ unsigned psum[257];
    __shared__ unsigned sBin, sCum, sLast;
    int bins = 1 << bits;
    for (int i = threadIdx.x; i < 2 * bins; i += blockDim.x) sh[i] = 0u;
    __syncthreads();

    int bid = blockIdx.x;
    int sel, nChunks, chunkId, N;
    const float* ptr;
    if (bid < 960) { sel = bid / 192; chunkId = bid % 192; nChunks = 192; ptr = w3 + sel * NW3; N = NW3; }
    else { int b2 = bid - 960; sel = 5 + b2 / 16; chunkId = b2 % 16; nChunks = 16; ptr = w1 + (b2 / 16) * NW1; N = NW1; }

    unsigned h0 = 0u, h1 = 0u;
    int hib = shift + bits;
    if (pass != 0) {
        h0 = g_prefix[sel][0] >> hib;
        h1 = g_prefix[sel][1] >> hib;
    }
    unsigned mask = (unsigned)(bins - 1);
    int per4 = (N / nChunks) >> 2;
    const float4* p4 = (const float4*)ptr;
    int start = chunkId * per4;
    int end = start + per4;

    for (int i = start + threadIdx.x; i < end; i += blockDim.x) {
        float4 v = p4[i];
        float c[4] = {v.x, v.y, v.z, v.w};
#pragma unroll
        for (int q = 0; q < 4; q++) {
            unsigned u = __float_as_uint(c[q]) & 0x7fffffffu;
            unsigned bin = (u >> shift) & mask;
            unsigned hi = u >> hib;
            if (hi == h0) atomicAdd(&sh[bin], 1u);
            if (hi == h1) atomicAdd(&sh[bins + bin], 1u);
        }
    }
    __syncthreads();
    for (int i = threadIdx.x; i < bins; i += blockDim.x) {
        unsigned a = sh[i], b = sh[bins + i];
        if (a) atomicAdd(&g_hist[sel][0][i], a);
        if (b) atomicAdd(&g_hist[sel][1][i], b);
    }

    __threadfence();
    if (threadIdx.x == 0) {
        unsigned old = atomicAdd(&g_done[pass][sel], 1u);
        sLast = (old == (unsigned)(nChunks - 1)) ? 1u : 0u;
    }
    __syncthreads();
    if (!sLast) return;

    int per = bins >> 8;
    int t = threadIdx.x;
    for (int r = 0; r < 2; r++) {
        unsigned rem = (pass == 0) ? ((r == 0) ? (unsigned)N / 2u - 1u : (unsigned)N / 2u)
                                   : g_remain[sel][r];
        unsigned cnt[8];
        unsigned local = 0;
        for (int j = 0; j < per; j++) {
            cnt[j] = g_hist[sel][r][t * per + j];
            g_hist[sel][r][t * per + j] = 0u;
            local += cnt[j];
        }
        psum[t] = local;
        __syncthreads();
        if (t == 0) { unsigned c = 0; for (int i = 0; i < 256; i++) { unsigned v = psum[i]; psum[i] = c; c += v; } }
        __syncthreads();
        unsigned base = psum[t];
        if (rem >= base && rem < base + local) {
            unsigned c = base;
            for (int j = 0; j < per; j++) {
                if (rem < c + cnt[j]) { sBin = (unsigned)(t * per + j); sCum = c; break; }
                c += cnt[j];
            }
        }
        __syncthreads();
        if (t == 0) {
            g_prefix[sel][r] = (pass == 0) ? (sBin << shift) : (g_prefix[sel][r] | (sBin << shift));
            g_remain[sel][r] = rem - sCum;
        }
        __syncthreads();
    }
    if (t == 0) {
        if (pass == 2) {
            float v0 = __uint_as_float(g_prefix[sel][0]);
            float v1 = __uint_as_float(g_prefix[sel][1]);
            g_scale[sel] = fmaxf(0.5f * (v0 + v1), 1e-5f);
        }
        g_done[pass][sel] = 0u;
    }
}

// ---------------- fused quantize + prepack + BN fold ----------------
__global__ void ph_quant_all(const float* __restrict__ w3, const float* __restrict__ w1,
                             const float* __restrict__ gamma, const float* __restrict__ beta,
                             const float* __restrict__ mean, const float* __restrict__ var) {
    __shared__ float tile[32][289];
    int B = blockIdx.x;
    int tid = threadIdx.x;
    if (B < 320) {
        int l = B / 64, rem = B % 64;
        int icb = rem / 8, ocb = rem % 8;
        int oc0 = ocb * 32, ic0 = icb * 32;
        const float* src = w3 + ((size_t)(l * 256 + oc0) * 256 + ic0) * 9;
        for (int j = tid; j < 32 * 288; j += 256) {
            int ocl = j / 288, r = j - ocl * 288;
            tile[ocl][r] = src[(size_t)ocl * 2304 + r];
        }
        __syncthreads();
        float s = g_scale[l];
        for (int j = tid; j < 9216; j += 256) {
            int ocl = j & 31, icl = (j >> 5) & 31, tap = j >> 10;
            float w = tile[ocl][icl * 9 + tap];
            g_w3h[((size_t)(l * 9 + tap) * 256 + ic0 + icl) * 256 + oc0 + ocl] =
                __float2half_rn(fminf(fmaxf(rintf(w / s), -1.f), 1.f));
        }
    } else if (B < 1600) {
        int i = (B - 320) * 256 + tid;
        int oc = i & 255;
        int ic = (i >> 8) & 255;
        int l  = i >> 16;
        float q = 0.f;
        if (oc < 255) {
            float s = g_scale[5 + l];
            float w = w1[(l * 255 + oc) * 256 + ic];
            q = fminf(fmaxf(rintf(w / s), -1.f), 1.f);
        }
        g_w1h[i] = __float2half_rn(q);
    } else {
        int i = (B - 1600) * 256 + tid;
        if (i < 1280) {
            int l = i >> 8;
            float inv = rsqrtf(var[i] + 1e-5f);
            g_scale3[i] = g_scale[l] * gamma[i] * inv;
            g_bias3[i]  = beta[i] - mean[i] * gamma[i] * inv;
        }
    }
}

// ---------------- fused input transform: NCHW fp32 -> padded NHWC fp16 ----------------
__global__ void ph_x_fused(const float* __restrict__ f0, const float* __restrict__ f1,
                           const float* __restrict__ f2, const float* __restrict__ f3,
                           const float* __restrict__ f4) {
    __shared__ float t[256 * 33];
    int tb = blockIdx.x;
    int lvl, tl;
    if (tb < 246)      { lvl = 0; tl = tb; }
    else if (tb < 330) { lvl = 1; tl = tb - 246; }
    else if (tb < 382) { lvl = 2; tl = tb - 330; }
    else if (tb < 400) { lvl = 3; tl = tb - 382; }
    else               { lvl = 4; tl = tb - 400; }
    const float* src = (lvl == 0) ? f0 : (lvl == 1) ? f1 : (lvl == 2) ? f2 : (lvl == 3) ? f3 : f4;
    int xc = c_XC[lvl];
    int x0 = (tl % xc) * 32, yp = tl / xc;
    int H = c_H[lvl], W = H, PW = c_PW[lvl];
    int xOff = c_xOff[lvl];
    int tid = threadIdx.x;
    int b = blockIdx.y;
    int xl = tid & 31;
    int ys = yp - 1;

    if (ys >= 0 && ys < H) {
        int xs = x0 + xl - 1;
        bool xv = (xs >= 0 && xs < W);
#pragma unroll 8
        for (int i = 0; i < 32; i++) {
            int ic = (tid >> 5) + i * 8;
            float v = xv ? src[((b * 256 + ic) * H + ys) * W + xs] : 0.f;
            t[ic * 33 + xl] = v;
        }
    } else {
#pragma unroll 8
        for (int i = 0; i < 32; i++) t[((tid >> 5) + i * 8) * 33 + xl] = 0.f;
    }
    __syncthreads();

    int ic0 = (tid & 31) * 8;
    for (int p = 0; p < 4; p++) {
        int xl2 = p * 8 + (tid >> 5);
        int xp = x0 + xl2;
        if (xp >= PW) continue;
        uint32_t hv[4];
#pragma unroll
        for (int j = 0; j < 4; j++) {
            float v0 = t[(ic0 + 2 * j) * 33 + xl2];
            float v1 = t[(ic0 + 2 * j + 1) * 33 + xl2];
            __half2 hh = __halves2half2(__float2half_rn(v0), __float2half_rn(v1));
            hv[j] = *(uint32_t*)&hh;
        }
        *(uint4*)(g_xh + xOff + ((b * c_PH[lvl] + yp) * PW + xp) * 256 + ic0) = *(uint4*)hv;
    }
}

// ---------------- fused conv3x3 + BN + SiLU (M=128, 256 thr, 2 blocks/SM, 3-tap groups) ----------------
__global__ void __launch_bounds__(256, 2) ph_conv3_fused() {
    extern __shared__ __align__(16) char smem[];
    int t = blockIdx.x;
    int lvl, tl;
    if (t < 50)      { lvl = 0; tl = t; }
    else if (t < 65) { lvl = 1; tl = t - 50; }
    else if (t < 71) { lvl = 2; tl = t - 65; }
    else if (t < 73) { lvl = 3; tl = t - 71; }
    else             { lvl = 4; tl = t - 73; }
    int TX = c_TX[lvl];
    int H = c_H[lvl], W = H, PH = c_PH[lvl], PW = c_PW[lvl];
    int xOff = c_xOff[lvl], hOff = c_hOff[lvl];

    int tid = threadIdx.x, wid = tid >> 5, lane = tid & 31;
    int b = blockIdx.y, oc0 = blockIdx.z * 128;
    int ty = tl / TX, tx0 = tl - ty * TX;
    int y0 = ty * 8, x0v = tx0 * 16;
    uint32_t sb = smem_u32(smem);

    float* sSC = (float*)smem;
    float* sBS = (float*)(smem + 1024);
    sSC[tid] = g_scale3[lvl * 256 + tid];
    sBS[tid] = g_bias3[lvl * 256 + tid];

    int mBase = (wid & 3) * 32, nBase = (wid >> 2) * 64;
    float acc[2][8][4];
#pragma unroll
    for (int i = 0; i < 2; i++)
#pragma unroll
        for (int j = 0; j < 8; j++)
#pragma unroll
            for (int q = 0; q < 4; q++) acc[i][j][q] = 0.f;

    const char* xh = (const char*)(g_xh + xOff);

    // A halo: one image, 180 rows (10y x 18x) x 64B, row stride 80
    auto issueA = [&](int ch) {
        uint32_t aB = sb + C3_A(ch & 1);
#pragma unroll
        for (int u = 0; u < 3; u++) {
            int idx = tid + u * 256;
            if (idx < 720) {
                int r = idx >> 2, c16 = idx & 3;
                int hy = r / 18, hx = r - hy * 18;
                int goff = (((b * PH + y0 + hy) * PW + x0v + hx) * 256 + ch * 32 + c16 * 8) * 2;
                cpa16(aB + r * 80 + c16 * 16, xh + goff);
            }
        }
    };
    // group G = 3 taps (ky = G%3, kx = 0..2) of ic-chunk ch = G/3
    auto issueG = [&](int G) {
        int ch = G / 3, g = G - ch * 3;
        if (g == 0) issueA(ch);
        uint32_t bB = sb + C3_B(G % 3);
        const __half* wb = g_w3h + ((lvl * 9 + g * 3) * 256 + ch * 32) * 256 + oc0;
#pragma unroll
        for (int tap = 0; tap < 3; tap++) {
#pragma unroll
            for (int u = 0; u < 2; u++) {
                int idx = tid + u * 256;
                int k = idx >> 4, c16 = idx & 15;
                cpa16(bB + tap * 8704 + k * 272 + c16 * 16, wb + tap * 65536 + k * 256 + c16 * 8);
            }
        }
        CP_COMMIT();
    };

    auto computeG = [&](int G) {
        int ch = G / 3, g = G - ch * 3;
        uint32_t aB = sb + C3_A(ch & 1);
        int lane16 = lane & 15;
        int khalf = (lane >> 4) << 4;
#pragma unroll
        for (int tap = 0; tap < 3; tap++) {
            uint32_t bB = sb + C3_B(G % 3) + tap * 8704;
            int ky = g, kx = tap;
#pragma unroll
            for (int ks = 0; ks < 2; ks++) {
                int k0 = ks * 16;
                uint32_t bf[8][2];
#pragma unroll
                for (int j = 0; j < 8; j++) {
                    uint32_t addr = bB + (k0 + lane16) * 272 + (nBase + j * 8) * 2;
                    asm volatile("ldmatrix.sync.aligned.m8n8.x2.trans.shared.b16 {%0,%1}, [%2];"
                                 : "=r"(bf[j][0]), "=r"(bf[j][1]) : "r"(addr));
                }
#pragma unroll
                for (int i = 0; i < 2; i++) {
                    int p = mBase + i * 16 + lane16;
                    int hr = ((p >> 4) + ky) * 18 + (p & 15) + kx;
                    uint32_t a0, a1, a2, a3;
                    uint32_t addr = aB + hr * 80 + k0 * 2 + khalf;
                    asm volatile("ldmatrix.sync.aligned.m8n8.x4.shared.b16 {%0,%1,%2,%3}, [%4];"
                                 : "=r"(a0), "=r"(a1), "=r"(a2), "=r"(a3) : "r"(addr));
#pragma unroll
                    for (int j = 0; j < 8; j++)
                        MMA16816(acc[i][j], a0, a1, a2, a3, bf[j][0], bf[j][1]);
                }
            }
        }
    };

    issueG(0);
    issueG(1);
    for (int G = 0; G < 24; G++) {
        if (G + 2 < 24) { issueG(G + 2); CP_WAIT2(); }
        else if (G + 1 < 24) { CP_WAIT1(); }
        else { CP_WAIT0(); }
        __syncthreads();
        computeG(G);
        __syncthreads();   // protect B buffer G%3 (rewritten at iteration G+1) from in-flight readers
    }

    int r0 = lane >> 2, cb = 2 * (lane & 3);
#pragma unroll
    for (int i = 0; i < 2; i++) {
#pragma unroll
        for (int half = 0; half < 2; half++) {
            int p = mBase + i * 16 + half * 8 + r0;
            int oy = y0 + (p >> 4), ox = x0v + (p & 15);
            if (oy < H && ox < W) {
                int e0 = hOff + (((b) * H + oy) * W + ox) * 256 + oc0;
#pragma unroll
                for (int j = 0; j < 8; j++) {
                    int ol = nBase + j * 8 + cb;
                    int oc = oc0 + ol;
                    float v0 = acc[i][j][half * 2]     * sSC[oc]     + sBS[oc];
                    float v1 = acc[i][j][half * 2 + 1] * sSC[oc + 1] + sBS[oc + 1];
                    v0 = v0 / (1.f + __expf(-v0));
                    v1 = v1 / (1.f + __expf(-v1));
                    __half2 hh = __halves2half2(__float2half_rn(v0), __float2half_rn(v1));
                    *(__half2*)(g_hh + e0 + ol) = hh;
                }
            }
        }
    }
}

// ---------------- fused conv1x1 + bias -> final layout (N=256 per block) ----------------
__global__ void __launch_bounds__(256) ph_conv1_fused(const float* __restrict__ b1,
                                                      float* __restrict__ out) {
    extern __shared__ __align__(16) char smem[];
    int t = blockIdx.x;
    int lvl, pb;
    if (t < 800)       { lvl = 0; pb = t; }
    else if (t < 1000) { lvl = 1; pb = t - 800; }
    else if (t < 1050) { lvl = 2; pb = t - 1000; }
    else if (t < 1063) { lvl = 3; pb = t - 1050; }
    else               { lvl = 4; pb = t - 1063; }
    int HW = c_HW[lvl], NP = BATCH * HW;
    int hOff = c_hOff[lvl], a85 = c_a85[lvl];
    int pxBase = pb * 128;

    int tid = threadIdx.x, wid = tid >> 5, lane = tid & 31;
    uint32_t sb = smem_u32(smem);

    float* sBI = (float*)smem;
    sBI[tid] = (tid < 255) ? b1[lvl * 255 + tid] : 0.f;
    float s1 = g_scale[5 + lvl];

    int mBase = (wid & 3) * 32, nBase = (wid >> 2) * 128;
    float acc[2][16][4];
#pragma unroll
    for (int i = 0; i < 2; i++)
#pragma unroll
        for (int j = 0; j < 16; j++)
#pragma unroll
            for (int q = 0; q < 4; q++) acc[i][j][q] = 0.f;

    auto issue = [&](int s) {
        int ch = s;
        uint32_t aB = sb + S1_A(s & 3);
        uint32_t bB = sb + S1_B(s & 3);
#pragma unroll
        for (int u = 0; u < 2; u++) {
            int idx = tid + u * 256;
            int r = idx >> 2, c16 = idx & 3;
            int p = pxBase + r;
            int sz = (p < NP) ? 16 : 0;
            int pc = (p < NP) ? p : 0;
            cpa16z(aB + r * 80 + c16 * 16, g_hh + hOff + pc * 256 + ch * 32 + c16 * 8, sz);
        }
        const __half* wb = g_w1h + (lvl * 256 + ch * 32) * 256;
#pragma unroll
        for (int u = 0; u < 4; u++) {
            int idx = tid + u * 256;
            int k = idx >> 5, c16 = idx & 31;
            cpa16(bB + k * 528 + c16 * 16, wb + k * 256 + c16 * 8);
        }
    };

    auto compute = [&](int s) {
        uint32_t aB = sb + S1_A(s & 3);
        uint32_t bB = sb + S1_B(s & 3);
        int lane16 = lane & 15;
        int khalf = (lane >> 4) << 4;
#pragma unroll
        for (int ks = 0; ks < 2; ks++) {
            int k0 = ks * 16;
            uint32_t a0[2], a1[2], a2[2], a3[2];
#pragma unroll
            for (int i = 0; i < 2; i++) {
                uint32_t addr = aB + (mBase + i * 16 + lane16) * 80 + k0 * 2 + khalf;
                asm volatile("ldmatrix.sync.aligned.m8n8.x4.shared.b16 {%0,%1,%2,%3}, [%4];"
                             : "=r"(a0[i]), "=r"(a1[i]), "=r"(a2[i]), "=r"(a3[i]) : "r"(addr));
            }
#pragma unroll
            for (int j = 0; j < 16; j++) {
                uint32_t bf0, bf1;
                uint32_t addr = bB + (k0 + lane16) * 528 + (nBase + j * 8) * 2;
                asm volatile("ldmatrix.sync.aligned.m8n8.x2.trans.shared.b16 {%0,%1}, [%2];"
                             : "=r"(bf0), "=r"(bf1) : "r"(addr));
#pragma unroll
                for (int i = 0; i < 2; i++)
                    MMA16816(acc[i][j], a0[i], a1[i], a2[i], a3[i], bf0, bf1);
            }
        }
    };

    issue(0); CP_COMMIT();
    issue(1); CP_COMMIT();
    for (int s = 0; s < 8; s++) {
        int nx = s + 2;
        if (nx < 8) { issue(nx); CP_COMMIT(); CP_WAIT2(); }
        else if (s + 1 < 8) { CP_WAIT1(); }
        else { CP_WAIT0(); }
        __syncthreads();
        compute(s);
    }

    int r0 = lane >> 2, cb = 2 * (lane & 3);
#pragma unroll
    for (int i = 0; i < 2; i++) {
#pragma unroll
        for (int half = 0; half < 2; half++) {
            int p = pxBase + mBase + i * 16 + half * 8 + r0;
            if (p < NP) {
                int bb = p / HW, hw = p - bb * HW;
                float* ob = out + bb * 2173875 + a85 + hw * 255;
#pragma unroll
                for (int j = 0; j < 16; j++) {
                    int oc = nBase + j * 8 + cb;
                    if (oc < 255)     ob[oc]     = acc[i][j][half * 2]     * s1 + sBI[oc];
                    if (oc + 1 < 255) ob[oc + 1] = acc[i][j][half * 2 + 1] * s1 + sBI[oc + 1];
                }
            }
        }
    }
}

// ---------------- launch ----------------
extern "C" void kernel_launch(void* const* d_in, const int* in_sizes, int n_in,
                              void* d_out, int out_size) {
    (void)in_sizes; (void)n_in; (void)out_size;
    const float* w3    = (const float*)d_in[5];
    const float* gamma = (const float*)d_in[6];
    const float* beta  = (const float*)d_in[7];
    const float* mean  = (const float*)d_in[8];
    const float* var   = (const float*)d_in[9];
    const float* w1    = (const float*)d_in[10];
    const float* b1    = (const float*)d_in[11];
    float* out = (float*)d_out;

    cudaFuncSetAttribute(ph_conv3_fused, cudaFuncAttributeMaxDynamicSharedMemorySize, SMEM_C3);
    cudaFuncSetAttribute(ph_conv1_fused, cudaFuncAttributeMaxDynamicSharedMemorySize, SMEM_C1);

    // Fork: median/quant chain on side stream, input transform on main stream.
    cudaStream_t s2;
    cudaEvent_t eF, eJ;
    cudaStreamCreate(&s2);
    cudaEventCreateWithFlags(&eF, cudaEventDisableTiming);
    cudaEventCreateWithFlags(&eJ, cudaEventDisableTiming);
    cudaEventRecord(eF, 0);
    cudaStreamWaitEvent(s2, eF, 0);

    ph_histscan<<<1040, 256, 2 * 2048 * sizeof(unsigned), s2>>>(w3, w1, 20, 11, 0);
    ph_histscan<<<1040, 256, 2 * 1024 * sizeof(unsigned), s2>>>(w3, w1, 10, 10, 1);
    ph_histscan<<<1040, 256, 2 * 1024 * sizeof(unsigned), s2>>>(w3, w1, 0, 10, 2);
    ph_quant_all<<<1605, 256, 0, s2>>>(w3, w1, gamma, beta, mean, var);

    ph_x_fused<<<dim3(410, 16), 256>>>((const float*)d_in[0], (const float*)d_in[1],
                                       (const float*)d_in[2], (const float*)d_in[3],
                                       (const float*)d_in[4]);

    // Join, then convs.
    cudaEventRecord(eJ, s2);
    cudaStreamWaitEvent(0, eJ, 0);

    ph_conv3_fused<<<dim3(74, 16, 2), 256, SMEM_C3>>>();
    ph_conv1_fused<<<1067, 256, SMEM_C1>>>(b1, out);
}

// round 17
// speedup vs baseline: 1.0814x; 1.0814x over previous
#include <cuda_runtime.h>
#include <cuda_fp16.h>
#include <cstdint>

#define BATCH 16
#define NW3   589824
#define NW1   65280

// ---------------- scratch ----------------
__device__ __half g_xh[41828352];           // padded NHWC input, fp16
__device__ __half g_hh[34918400];           // hidden NHWC, fp16
__device__ __half g_w3h[5 * 9 * 256 * 256]; // [lvl][tap][ic][oc] ternary fp16
__device__ __half g_w1h[5 * 256 * 256];     // [lvl][ic][oc(255->0 pad)]
__device__ float    g_scale3[5 * 256];
__device__ float    g_bias3 [5 * 256];
__device__ float    g_scale[10];
__device__ unsigned g_hist[10][2][2048];
__device__ unsigned g_prefix[10][2];
__device__ unsigned g_remain[10][2];
__device__ unsigned g_done[3][10];

// ---------------- compile-time per-level tables ----------------
__constant__ int c_H[5]    = {80, 40, 20, 10, 5};
__constant__ int c_PH[5]   = {82, 42, 26, 18, 10};
__constant__ int c_PW[5]   = {82, 50, 34, 18, 18};
__constant__ int c_TX[5]   = {5, 3, 2, 1, 1};
__constant__ int c_xOff[5] = {0, 27541504, 36143104, 39763968, 41091072};
__constant__ int c_hOff[5] = {0, 26214400, 32768000, 34406400, 34816000};
__constant__ int c_a85[5]  = {0, 1632000, 2040000, 2142000, 2167500};
__constant__ int c_HW[5]   = {6400, 1600, 400, 100, 25};
__constant__ int c_XC[5]   = {3, 2, 2, 1, 1};

__device__ __forceinline__ uint32_t smem_u32(const void* p) {
    uint32_t a;
    asm("{ .reg .u64 t; cvta.to.shared.u64 t, %1; cvt.u32.u64 %0, t; }" : "=r"(a) : "l"(p));
    return a;
}
#define CP_COMMIT() asm volatile("cp.async.commit_group;" ::: "memory")
#define CP_WAIT2()  asm volatile("cp.async.wait_group 2;" ::: "memory")
#define CP_WAIT1()  asm volatile("cp.async.wait_group 1;" ::: "memory")
#define CP_WAIT0()  asm volatile("cp.async.wait_group 0;" ::: "memory")
__device__ __forceinline__ void cpa16(uint32_t dst, const void* src) {
    asm volatile("cp.async.ca.shared.global [%0], [%1], 16;" :: "r"(dst), "l"(src) : "memory");
}
__device__ __forceinline__ void cpa16z(uint32_t dst, const void* src, int sz) {
    asm volatile("cp.async.ca.shared.global [%0], [%1], 16, %2;" :: "r"(dst), "l"(src), "r"(sz) : "memory");
}
#define MMA16816(c, a0, a1, a2, a3, b0, b1)                              \
    asm volatile("mma.sync.aligned.m16n8k16.row.col.f32.f16.f16.f32 "    \
        "{%0,%1,%2,%3}, {%4,%5,%6,%7}, {%8,%9}, {%0,%1,%2,%3};"          \
        : "+f"((c)[0]), "+f"((c)[1]), "+f"((c)[2]), "+f"((c)[3])         \
        : "r"(a0), "r"(a1), "r"(a2), "r"(a3), "r"(b0), "r"(b1))

// conv3 smem: sc(1024)|bs(1024) | A buf0/1 (28800 each: 360 rows x 80B) | B group buf0..3 (26112 each = 3 taps)
#define C3_A(b)     (2048 + (b) * 28800)
#define C3_B(b)     (59648 + (b) * 26112)
#define SMEM_C3     164096
// conv1 smem: bi(2048) | A buf0..3 (10240 each: 128 rows x 80B) | B buf0..3 (16896 each: 32k x 256oc, row 528B)
#define S1_A(b)     (2048 + (b) * 10240)
#define S1_B(b)     (43008 + (b) * 16896)
#define SMEM_C1     110592

// ---------------- median radix-select: hist + last-block scan fused ----------------
__global__ void ph_histscan(const float* __restrict__ w3, const float* __restrict__ w1,
                            int shift, int bits, int pass) {
    extern __shared__ unsigned sh[];
    __shared__ unsigned psum[257];
    __shared__ unsigned sBin, sCum, sLast;
    int bins = 1 << bits;
    for (int i = threadIdx.x; i < 2 * bins; i += blockDim.x) sh[i] = 0u;
    __syncthreads();

    int bid = blockIdx.x;
    int sel, nChunks, chunkId, N;
    const float* ptr;
    if (bid < 960) { sel = bid / 192; chunkId = bid % 192; nChunks = 192; ptr = w3 + sel * NW3; N = NW3; }
    else { int b2 = bid - 960; sel = 5 + b2 / 16; chunkId = b2 % 16; nChunks = 16; ptr = w1 + (b2 / 16) * NW1; N = NW1; }

    unsigned h0 = 0u, h1 = 0u;
    int hib = shift + bits;
    if (pass != 0) {
        h0 = g_prefix[sel][0] >> hib;
        h1 = g_prefix[sel][1] >> hib;
    }
    unsigned mask = (unsigned)(bins - 1);
    int per4 = (N / nChunks) >> 2;
    const float4* p4 = (const float4*)ptr;
    int start = chunkId * per4;
    int end = start + per4;

    for (int i = start + threadIdx.x; i < end; i += blockDim.x) {
        float4 v = p4[i];
        float c[4] = {v.x, v.y, v.z, v.w};
#pragma unroll
        for (int q = 0; q < 4; q++) {
            unsigned u = __float_as_uint(c[q]) & 0x7fffffffu;
            unsigned bin = (u >> shift) & mask;
            unsigned hi = u >> hib;
            if (hi == h0) atomicAdd(&sh[bin], 1u);
            if (hi == h1) atomicAdd(&sh[bins + bin], 1u);
        }
    }
    __syncthreads();
    for (int i = threadIdx.x; i < bins; i += blockDim.x) {
        unsigned a = sh[i], b = sh[bins + i];
        if (a) atomicAdd(&g_hist[sel][0][i], a);
        if (b) atomicAdd(&g_hist[sel][1][i], b);
    }

    __threadfence();
    if (threadIdx.x == 0) {
        unsigned old = atomicAdd(&g_done[pass][sel], 1u);
        sLast = (old == (unsigned)(nChunks - 1)) ? 1u : 0u;
    }
    __syncthreads();
    if (!sLast) return;

    int per = bins >> 8;
    int t = threadIdx.x;
    for (int r = 0; r < 2; r++) {
        unsigned rem = (pass == 0) ? ((r == 0) ? (unsigned)N / 2u - 1u : (unsigned)N / 2u)
                                   : g_remain[sel][r];
        unsigned cnt[8];
        unsigned local = 0;
        for (int j = 0; j < per; j++) {
            cnt[j] = g_hist[sel][r][t * per + j];
            g_hist[sel][r][t * per + j] = 0u;
            local += cnt[j];
        }
        psum[t] = local;
        __syncthreads();
        if (t == 0) { unsigned c = 0; for (int i = 0; i < 256; i++) { unsigned v = psum[i]; psum[i] = c; c += v; } }
        __syncthreads();
        unsigned base = psum[t];
        if (rem >= base && rem < base + local) {
            unsigned c = base;
            for (int j = 0; j < per; j++) {
                if (rem < c + cnt[j]) { sBin = (unsigned)(t * per + j); sCum = c; break; }
                c += cnt[j];
            }
        }
        __syncthreads();
        if (t == 0) {
            g_prefix[sel][r] = (pass == 0) ? (sBin << shift) : (g_prefix[sel][r] | (sBin << shift));
            g_remain[sel][r] = rem - sCum;
        }
        __syncthreads();
    }
    if (t == 0) {
        if (pass == 2) {
            float v0 = __uint_as_float(g_prefix[sel][0]);
            float v1 = __uint_as_float(g_prefix[sel][1]);
            g_scale[sel] = fmaxf(0.5f * (v0 + v1), 1e-5f);
        }
        g_done[pass][sel] = 0u;
    }
}

// ---------------- fused quantize + prepack + BN fold ----------------
__global__ void ph_quant_all(const float* __restrict__ w3, const float* __restrict__ w1,
                             const float* __restrict__ gamma, const float* __restrict__ beta,
                             const float* __restrict__ mean, const float* __restrict__ var) {
    __shared__ float tile[32][289];
    int B = blockIdx.x;
    int tid = threadIdx.x;
    if (B < 320) {
        int l = B / 64, rem = B % 64;
        int icb = rem / 8, ocb = rem % 8;
        int oc0 = ocb * 32, ic0 = icb * 32;
        const float* src = w3 + ((size_t)(l * 256 + oc0) * 256 + ic0) * 9;
        for (int j = tid; j < 32 * 288; j += 256) {
            int ocl = j / 288, r = j - ocl * 288;
            tile[ocl][r] = src[(size_t)ocl * 2304 + r];
        }
        __syncthreads();
        float s = g_scale[l];
        for (int j = tid; j < 9216; j += 256) {
            int ocl = j & 31, icl = (j >> 5) & 31, tap = j >> 10;
            float w = tile[ocl][icl * 9 + tap];
            g_w3h[((size_t)(l * 9 + tap) * 256 + ic0 + icl) * 256 + oc0 + ocl] =
                __float2half_rn(fminf(fmaxf(rintf(w / s), -1.f), 1.f));
        }
    } else if (B < 1600) {
        int i = (B - 320) * 256 + tid;
        int oc = i & 255;
        int ic = (i >> 8) & 255;
        int l  = i >> 16;
        float q = 0.f;
        if (oc < 255) {
            float s = g_scale[5 + l];
            float w = w1[(l * 255 + oc) * 256 + ic];
            q = fminf(fmaxf(rintf(w / s), -1.f), 1.f);
        }
        g_w1h[i] = __float2half_rn(q);
    } else {
        int i = (B - 1600) * 256 + tid;
        if (i < 1280) {
            int l = i >> 8;
            float inv = rsqrtf(var[i] + 1e-5f);
            g_scale3[i] = g_scale[l] * gamma[i] * inv;
            g_bias3[i]  = beta[i] - mean[i] * gamma[i] * inv;
        }
    }
}

// ---------------- fused input transform: NCHW fp32 -> padded NHWC fp16 ----------------
__global__ void ph_x_fused(const float* __restrict__ f0, const float* __restrict__ f1,
                           const float* __restrict__ f2, const float* __restrict__ f3,
                           const float* __restrict__ f4) {
    __shared__ float t[256 * 33];
    int tb = blockIdx.x;
    int lvl, tl;
    if (tb < 246)      { lvl = 0; tl = tb; }
    else if (tb < 330) { lvl = 1; tl = tb - 246; }
    else if (tb < 382) { lvl = 2; tl = tb - 330; }
    else if (tb < 400) { lvl = 3; tl = tb - 382; }
    else               { lvl = 4; tl = tb - 400; }
    const float* src = (lvl == 0) ? f0 : (lvl == 1) ? f1 : (lvl == 2) ? f2 : (lvl == 3) ? f3 : f4;
    int xc = c_XC[lvl];
    int x0 = (tl % xc) * 32, yp = tl / xc;
    int H = c_H[lvl], W = H, PW = c_PW[lvl];
    int xOff = c_xOff[lvl];
    int tid = threadIdx.x;
    int b = blockIdx.y;
    int xl = tid & 31;
    int ys = yp - 1;

    if (ys >= 0 && ys < H) {
        int xs = x0 + xl - 1;
        bool xv = (xs >= 0 && xs < W);
#pragma unroll 8
        for (int i = 0; i < 32; i++) {
            int ic = (tid >> 5) + i * 8;
            float v = xv ? src[((b * 256 + ic) * H + ys) * W + xs] : 0.f;
            t[ic * 33 + xl] = v;
        }
    } else {
#pragma unroll 8
        for (int i = 0; i < 32; i++) t[((tid >> 5) + i * 8) * 33 + xl] = 0.f;
    }
    __syncthreads();

    int ic0 = (tid & 31) * 8;
    for (int p = 0; p < 4; p++) {
        int xl2 = p * 8 + (tid >> 5);
        int xp = x0 + xl2;
        if (xp >= PW) continue;
        uint32_t hv[4];
#pragma unroll
        for (int j = 0; j < 4; j++) {
            float v0 = t[(ic0 + 2 * j) * 33 + xl2];
            float v1 = t[(ic0 + 2 * j + 1) * 33 + xl2];
            __half2 hh = __halves2half2(__float2half_rn(v0), __float2half_rn(v1));
            hv[j] = *(uint32_t*)&hh;
        }
        *(uint4*)(g_xh + xOff + ((b * c_PH[lvl] + yp) * PW + xp) * 256 + ic0) = *(uint4*)hv;
    }
}

// ---------------- fused conv3x3 + BN + SiLU (M=256, 512 thr / 16 warps, 3-tap groups) ----------------
__global__ void __launch_bounds__(512, 1) ph_conv3_fused() {
    extern __shared__ __align__(16) char smem[];
    int t = blockIdx.x;
    int lvl, tl;
    if (t < 50)      { lvl = 0; tl = t; }
    else if (t < 65) { lvl = 1; tl = t - 50; }
    else if (t < 71) { lvl = 2; tl = t - 65; }
    else if (t < 73) { lvl = 3; tl = t - 71; }
    else             { lvl = 4; tl = t - 73; }
    int TX = c_TX[lvl];
    int H = c_H[lvl], W = H, PH = c_PH[lvl], PW = c_PW[lvl];
    int xOff = c_xOff[lvl], hOff = c_hOff[lvl];

    int tid = threadIdx.x, wid = tid >> 5, lane = tid & 31;
    int b0 = blockIdx.y * 2, oc0 = blockIdx.z * 128;
    int ty = tl / TX, tx0 = tl - ty * TX;
    int y0 = ty * 8, x0v = tx0 * 16;
    uint32_t sb = smem_u32(smem);

    float* sSC = (float*)smem;
    float* sBS = (float*)(smem + 1024);
    if (tid < 256) {
        sSC[tid] = g_scale3[lvl * 256 + tid];
        sBS[tid] = g_bias3[lvl * 256 + tid];
    }

    int mBase = (wid & 3) * 64, nBase = (wid >> 2) * 32;
    float acc[4][4][4];
#pragma unroll
    for (int i = 0; i < 4; i++)
#pragma unroll
        for (int j = 0; j < 4; j++)
#pragma unroll
            for (int q = 0; q < 4; q++) acc[i][j][q] = 0.f;

    const char* xh = (const char*)(g_xh + xOff);

    auto issueA = [&](int ch) {
        uint32_t aB = sb + C3_A(ch & 1);
#pragma unroll
        for (int u = 0; u < 3; u++) {
            int idx = tid + u * 512;
            if (idx < 1440) {
                int img = idx / 720, rest = idx % 720;
                int r = rest >> 2, c16 = rest & 3;
                int hy = r / 18, hx = r - hy * 18;
                int goff = ((((b0 + img) * PH + y0 + hy) * PW + x0v + hx) * 256 + ch * 32 + c16 * 8) * 2;
                cpa16(aB + (img * 180 + r) * 80 + c16 * 16, xh + goff);
            }
        }
    };
    // group G = 3 taps (ky = G%3, kx = 0..2) of ic-chunk ch = G/3
    auto issueG = [&](int G) {
        int ch = G / 3, g = G - ch * 3;
        if (g == 0) issueA(ch);
        uint32_t bB = sb + C3_B(G & 3);
        const __half* wb = g_w3h + ((lvl * 9 + g * 3) * 256 + ch * 32) * 256 + oc0;
        int k = tid >> 4, c16 = tid & 15;
#pragma unroll
        for (int tap = 0; tap < 3; tap++)
            cpa16(bB + tap * 8704 + k * 272 + c16 * 16, wb + tap * 65536 + k * 256 + c16 * 8);
        CP_COMMIT();
    };

    auto computeG = [&](int G) {
        int ch = G / 3, g = G - ch * 3;
        uint32_t aB = sb + C3_A(ch & 1);
        int lane16 = lane & 15;
        int khalf = (lane >> 4) << 4;
#pragma unroll
        for (int tap = 0; tap < 3; tap++) {
            uint32_t bB = sb + C3_B(G & 3) + tap * 8704;
            int ky = g, kx = tap;
#pragma unroll
            for (int ks = 0; ks < 2; ks++) {
                int k0 = ks * 16;
                uint32_t bf[4][2];
#pragma unroll
                for (int j = 0; j < 4; j++) {
                    uint32_t addr = bB + (k0 + lane16) * 272 + (nBase + j * 8) * 2;
                    asm volatile("ldmatrix.sync.aligned.m8n8.x2.trans.shared.b16 {%0,%1}, [%2];"
                                 : "=r"(bf[j][0]), "=r"(bf[j][1]) : "r"(addr));
                }
#pragma unroll
                for (int i = 0; i < 4; i++) {
                    int p = mBase + i * 16 + lane16;
                    int img = p >> 7, p7 = p & 127;
                    int hr = img * 180 + ((p7 >> 4) + ky) * 18 + (p7 & 15) + kx;
                    uint32_t a0, a1, a2, a3;
                    uint32_t addr = aB + hr * 80 + k0 * 2 + khalf;
                    asm volatile("ldmatrix.sync.aligned.m8n8.x4.shared.b16 {%0,%1,%2,%3}, [%4];"
                                 : "=r"(a0), "=r"(a1), "=r"(a2), "=r"(a3) : "r"(addr));
#pragma unroll
                    for (int j = 0; j < 4; j++)
                        MMA16816(acc[i][j], a0, a1, a2, a3, bf[j][0], bf[j][1]);
                }
            }
        }
    };

    issueG(0);
    issueG(1);
    for (int G = 0; G < 24; G++) {
        if (G + 2 < 24) { issueG(G + 2); CP_WAIT2(); }
        else if (G + 1 < 24) { CP_WAIT1(); }
        else { CP_WAIT0(); }
        __syncthreads();
        computeG(G);
    }

    __syncthreads();
    int r0 = lane >> 2, cb = 2 * (lane & 3);
#pragma unroll
    for (int i = 0; i < 4; i++) {
#pragma unroll
        for (int half = 0; half < 2; half++) {
            int p = mBase + i * 16 + half * 8 + r0;
            int img = p >> 7, p7 = p & 127;
            int oy = y0 + (p7 >> 4), ox = x0v + (p7 & 15);
            if (oy < H && ox < W) {
                int e0 = hOff + (((b0 + img) * H + oy) * W + ox) * 256 + oc0;
#pragma unroll
                for (int j = 0; j < 4; j++) {
                    int ol = nBase + j * 8 + cb;
                    int oc = oc0 + ol;
                    float v0 = acc[i][j][half * 2]     * sSC[oc]     + sBS[oc];
                    float v1 = acc[i][j][half * 2 + 1] * sSC[oc + 1] + sBS[oc + 1];
                    v0 = v0 / (1.f + __expf(-v0));
                    v1 = v1 / (1.f + __expf(-v1));
                    __half2 hh = __halves2half2(__float2half_rn(v0), __float2half_rn(v1));
                    *(__half2*)(g_hh + e0 + ol) = hh;
                }
            }
        }
    }
}

// ---------------- fused conv1x1 + bias -> final layout (512 thr, warp tile 32px x 64oc) ----------------
__global__ void __launch_bounds__(512, 1) ph_conv1_fused(const float* __restrict__ b1,
                                                         float* __restrict__ out) {
    extern __shared__ __align__(16) char smem[];
    int t = blockIdx.x;
    int lvl, pb;
    if (t < 800)       { lvl = 0; pb = t; }
    else if (t < 1000) { lvl = 1; pb = t - 800; }
    else if (t < 1050) { lvl = 2; pb = t - 1000; }
    else if (t < 1063) { lvl = 3; pb = t - 1050; }
    else               { lvl = 4; pb = t - 1063; }
    int HW = c_HW[lvl], NP = BATCH * HW;
    int hOff = c_hOff[lvl], a85 = c_a85[lvl];
    int pxBase = pb * 128;

    int tid = threadIdx.x, wid = tid >> 5, lane = tid & 31;
    uint32_t sb = smem_u32(smem);

    float* sBI = (float*)smem;
    if (tid < 256) sBI[tid] = (tid < 255) ? b1[lvl * 255 + tid] : 0.f;
    float s1 = g_scale[5 + lvl];

    int mBase = (wid & 3) * 32, nBase = (wid >> 2) * 64;
    float acc[2][8][4];
#pragma unroll
    for (int i = 0; i < 2; i++)
#pragma unroll
        for (int j = 0; j < 8; j++)
#pragma unroll
            for (int q = 0; q < 4; q++) acc[i][j][q] = 0.f;

    auto issue = [&](int s) {
        int ch = s;
        uint32_t aB = sb + S1_A(s & 3);
        uint32_t bB = sb + S1_B(s & 3);
        {
            int r = tid >> 2, c16 = tid & 3;      // 512 = 128 rows x 4 vec
            int p = pxBase + r;
            int sz = (p < NP) ? 16 : 0;
            int pc = (p < NP) ? p : 0;
            cpa16z(aB + r * 80 + c16 * 16, g_hh + hOff + pc * 256 + ch * 32 + c16 * 8, sz);
        }
        const __half* wb = g_w1h + (lvl * 256 + ch * 32) * 256;
#pragma unroll
        for (int u = 0; u < 2; u++) {
            int idx = tid + u * 512;              // 1024 = 32 k x 32 vec
            int k = idx >> 5, c16 = idx & 31;
            cpa16(bB + k * 528 + c16 * 16, wb + k * 256 + c16 * 8);
        }
    };

    auto compute = [&](int s) {
        uint32_t aB = sb + S1_A(s & 3);
        uint32_t bB = sb + S1_B(s & 3);
        int lane16 = lane & 15;
        int khalf = (lane >> 4) << 4;
#pragma unroll
        for (int ks = 0; ks < 2; ks++) {
            int k0 = ks * 16;
            uint32_t a0[2], a1[2], a2[2], a3[2];
#pragma unroll
            for (int i = 0; i < 2; i++) {
                uint32_t addr = aB + (mBase + i * 16 + lane16) * 80 + k0 * 2 + khalf;
                asm volatile("ldmatrix.sync.aligned.m8n8.x4.shared.b16 {%0,%1,%2,%3}, [%4];"
                             : "=r"(a0[i]), "=r"(a1[i]), "=r"(a2[i]), "=r"(a3[i]) : "r"(addr));
            }
#pragma unroll
            for (int j = 0; j < 8; j++) {
                uint32_t bf0, bf1;
                uint32_t addr = bB + (k0 + lane16) * 528 + (nBase + j * 8) * 2;
                asm volatile("ldmatrix.sync.aligned.m8n8.x2.trans.shared.b16 {%0,%1}, [%2];"
                             : "=r"(bf0), "=r"(bf1) : "r"(addr));
#pragma unroll
                for (int i = 0; i < 2; i++)
                    MMA16816(acc[i][j], a0[i], a1[i], a2[i], a3[i], bf0, bf1);
            }
        }
    };

    issue(0); CP_COMMIT();
    issue(1); CP_COMMIT();
    for (int s = 0; s < 8; s++) {
        int nx = s + 2;
        if (nx < 8) { issue(nx); CP_COMMIT(); CP_WAIT2(); }
        else if (s + 1 < 8) { CP_WAIT1(); }
        else { CP_WAIT0(); }
        __syncthreads();
        compute(s);
    }

    int r0 = lane >> 2, cb = 2 * (lane & 3);
#pragma unroll
    for (int i = 0; i < 2; i++) {
#pragma unroll
        for (int half = 0; half < 2; half++) {
            int p = pxBase + mBase + i * 16 + half * 8 + r0;
            if (p < NP) {
                int bb = p / HW, hw = p - bb * HW;
                float* ob = out + bb * 2173875 + a85 + hw * 255;
#pragma unroll
                for (int j = 0; j < 8; j++) {
                    int oc = nBase + j * 8 + cb;
                    if (oc < 255)     ob[oc]     = acc[i][j][half * 2]     * s1 + sBI[oc];
                    if (oc + 1 < 255) ob[oc + 1] = acc[i][j][half * 2 + 1] * s1 + sBI[oc + 1];
                }
            }
        }
    }
}

// ---------------- launch ----------------
extern "C" void kernel_launch(void* const* d_in, const int* in_sizes, int n_in,
                              void* d_out, int out_size) {
    (void)in_sizes; (void)n_in; (void)out_size;
    const float* w3    = (const float*)d_in[5];
    const float* gamma = (const float*)d_in[6];
    const float* beta  = (const float*)d_in[7];
    const float* mean  = (const float*)d_in[8];
    const float* var   = (const float*)d_in[9];
    const float* w1    = (const float*)d_in[10];
    const float* b1    = (const float*)d_in[11];
    float* out = (float*)d_out;

    cudaFuncSetAttribute(ph_conv3_fused, cudaFuncAttributeMaxDynamicSharedMemorySize, SMEM_C3);
    cudaFuncSetAttribute(ph_conv1_fused, cudaFuncAttributeMaxDynamicSharedMemorySize, SMEM_C1);

    // Fork: median/quant chain on side stream, input transform on main stream.
    cudaStream_t s2;
    cudaEvent_t eF, eJ;
    cudaStreamCreate(&s2);
    cudaEventCreateWithFlags(&eF, cudaEventDisableTiming);
    cudaEventCreateWithFlags(&eJ, cudaEventDisableTiming);
    cudaEventRecord(eF, 0);
    cudaStreamWaitEvent(s2, eF, 0);

    ph_histscan<<<1040, 256, 2 * 2048 * sizeof(unsigned), s2>>>(w3, w1, 20, 11, 0);
    ph_histscan<<<1040, 256, 2 * 1024 * sizeof(unsigned), s2>>>(w3, w1, 10, 10, 1);
    ph_histscan<<<1040, 256, 2 * 1024 * sizeof(unsigned), s2>>>(w3, w1, 0, 10, 2);
    ph_quant_all<<<1605, 256, 0, s2>>>(w3, w1, gamma, beta, mean, var);

    ph_x_fused<<<dim3(410, 16), 256>>>((const float*)d_in[0], (const float*)d_in[1],
                                       (const float*)d_in[2], (const float*)d_in[3],
                                       (const float*)d_in[4]);

    // Join, then convs.
    cudaEventRecord(eJ, s2);
    cudaStreamWaitEvent(0, eJ, 0);

    ph_conv3_fused<<<dim3(74, 8, 2), 512, SMEM_C3>>>();
    ph_conv1_fused<<<1067, 512, SMEM_C1>>>(b1, out);
}